// round 2
// baseline (speedup 1.0000x reference)
#include <cuda_runtime.h>

#define NN 100000
#define NE 3200000
#define HID 64

// ---------------- scratch (device globals; no allocation) ----------------
__device__ int   g_is64;
__device__ int   g_cnt[NN];
__device__ int   g_off[NN + 1];
__device__ int   g_off2[NN];
__device__ int   g_csr[NE];
__device__ float g_mean[(size_t)NN * HID];
__device__ float g_mtau[NN];
__device__ float g_h1[(size_t)NN * HID];

// ---------------- edge-index dtype detection ----------------
// Reference requests int64 but JAX default config downcasts to int32.
// Genuine int64 node ids are always in [0, NN); int32 data misread as int64
// has a random node id in the high word -> out of range almost surely.
__global__ void detect_kernel(const long long* __restrict__ ei) {
    int lane = threadIdx.x;
    int ok = 1;
    for (int i = lane; i < 4096; i += 32) {
        long long v = ei[i];
        if (v < 0 || v >= NN) ok = 0;
    }
    unsigned b = __ballot_sync(0xffffffffu, ok);
    if (lane == 0) g_is64 = (b == 0xffffffffu) ? 1 : 0;
}

__device__ __forceinline__ int edge_at(const void* eiv, long long idx) {
    if (g_is64) return (int)((const long long*)eiv)[idx];
    return ((const int*)eiv)[idx];
}

// ---------------- CSR build ----------------
__global__ void zero_cnt_kernel() {
    int i = blockIdx.x * blockDim.x + threadIdx.x;
    if (i < NN) g_cnt[i] = 0;
}

__global__ void deg_kernel(const void* __restrict__ eiv) {
    int e = blockIdx.x * blockDim.x + threadIdx.x;
    if (e < NE) {
        int dst = edge_at(eiv, (long long)NE + e);
        if ((unsigned)dst < NN) atomicAdd(&g_cnt[dst], 1);
    }
}

// single-block exclusive scan over g_cnt -> g_off (and copy g_off2)
__global__ void scan_kernel() {
    __shared__ int wsum[32];
    __shared__ int s_carry;
    int tid = threadIdx.x, lane = tid & 31, w = tid >> 5;
    if (tid == 0) s_carry = 0;
    __syncthreads();
    for (int base = 0; base < NN; base += 1024) {
        int i = base + tid;
        int v = (i < NN) ? g_cnt[i] : 0;
        int xv = v;
#pragma unroll
        for (int d = 1; d < 32; d <<= 1) {
            int y = __shfl_up_sync(0xffffffffu, xv, d);
            if (lane >= d) xv += y;
        }
        if (lane == 31) wsum[w] = xv;
        __syncthreads();
        if (w == 0) {
            int s = wsum[lane];
#pragma unroll
            for (int d = 1; d < 32; d <<= 1) {
                int y = __shfl_up_sync(0xffffffffu, s, d);
                if (lane >= d) s += y;
            }
            wsum[lane] = s;
        }
        __syncthreads();
        int incl = xv + (w ? wsum[w - 1] : 0) + s_carry;
        if (i < NN) { g_off[i] = incl - v; g_off2[i] = incl - v; }
        __syncthreads();
        if (tid == 1023) s_carry = incl;
        __syncthreads();
    }
    if (tid == 0) g_off[NN] = s_carry;
}

__global__ void fill_kernel(const void* __restrict__ eiv) {
    int e = blockIdx.x * blockDim.x + threadIdx.x;
    if (e < NE) {
        int src = edge_at(eiv, e);
        int dst = edge_at(eiv, (long long)NE + e);
        if ((unsigned)dst < NN && (unsigned)src < NN) {
            int p = atomicAdd(&g_off2[dst], 1);
            if ((unsigned)p < NE) g_csr[p] = src;
        }
    }
}

// ---------------- aggregation: warp per node, mean of 64-dim rows (+tau) ----------------
template <bool TAU>
__global__ void agg_kernel(const float* __restrict__ featp,
                           const float* __restrict__ tau) {
    const float* __restrict__ feat = TAU ? featp : (const float*)g_h1;
    int lane = threadIdx.x & 31;
    int n = (blockIdx.x * blockDim.x + threadIdx.x) >> 5;
    if (n >= NN) return;
    int beg = g_off[n], end = g_off[n + 1];
    float a0 = 0.f, a1 = 0.f, at = 0.f;
    int j = beg;
    int nfull = (end - beg) >> 5;
    for (int c = 0; c < nfull; c++, j += 32) {
        int s = g_csr[j + lane];
        if (TAU) at += __ldg(tau + s);
#pragma unroll
        for (int k = 0; k < 32; k++) {
            int si = __shfl_sync(0xffffffffu, s, k);
            float2 v = *(const float2*)(feat + (size_t)si * HID + 2 * lane);
            a0 += v.x; a1 += v.y;
        }
    }
    int rem = end - j;
    if (rem > 0) {
        int s = (lane < rem) ? g_csr[j + lane] : 0;
        if (TAU && lane < rem) at += __ldg(tau + s);
        for (int k = 0; k < rem; k++) {
            int si = __shfl_sync(0xffffffffu, s, k);
            float2 v = *(const float2*)(feat + (size_t)si * HID + 2 * lane);
            a0 += v.x; a1 += v.y;
        }
    }
    float inv = 1.f / fmaxf((float)(end - beg), 1.f);
    float2 o; o.x = a0 * inv; o.y = a1 * inv;
    *(float2*)(g_mean + (size_t)n * HID + 2 * lane) = o;
    if (TAU) {
#pragma unroll
        for (int d = 16; d; d >>= 1) at += __shfl_xor_sync(0xffffffffu, at, d);
        if (lane == 0) g_mtau[n] = at * inv;
    }
}

// ---------------- layer-1 GEMM: h1 = relu(mean@W1l[0:64] + mtau*W1l[64] + x@W1r[0:64] + tau*W1r[64] + b1l) ----------------
__global__ __launch_bounds__(256) void gemm1_kernel(
    const float* __restrict__ x, const float* __restrict__ tau,
    const float* __restrict__ W1l, const float* __restrict__ b1l,
    const float* __restrict__ W1r) {
    __shared__ __align__(16) float sWl[65 * HID];
    __shared__ __align__(16) float sWr[65 * HID];
    __shared__ float sBias[HID];
    __shared__ __align__(16) float sA[8][136];
    int tid = threadIdx.x;
    for (int i = tid; i < 65 * HID; i += 256) { sWl[i] = W1l[i]; sWr[i] = W1r[i]; }
    if (tid < HID) sBias[tid] = b1l[tid];
    int n0 = blockIdx.x * 128;
    int cg = tid & 15, ng = tid >> 4;
    float acc[8][4];
#pragma unroll
    for (int i = 0; i < 8; i++)
#pragma unroll
        for (int c = 0; c < 4; c++) acc[i][c] = 0.f;
    int ldn = n0 + (tid >> 1);
    int ldk = (tid & 1) * 4;
    for (int pass = 0; pass < 2; pass++) {
        const float* __restrict__ A = pass ? x : (const float*)g_mean;
        const float* W = pass ? sWr : sWl;
        for (int kb = 0; kb < HID; kb += 8) {
            __syncthreads();
            float4 v = make_float4(0.f, 0.f, 0.f, 0.f);
            if (ldn < NN) v = *(const float4*)(A + (size_t)ldn * HID + kb + ldk);
            sA[ldk + 0][tid >> 1] = v.x; sA[ldk + 1][tid >> 1] = v.y;
            sA[ldk + 2][tid >> 1] = v.z; sA[ldk + 3][tid >> 1] = v.w;
            __syncthreads();
#pragma unroll
            for (int kk = 0; kk < 8; kk++) {
                float4 b  = *(const float4*)(W + (kb + kk) * HID + 4 * cg);
                float4 q0 = *(const float4*)(&sA[kk][8 * ng]);
                float4 q1 = *(const float4*)(&sA[kk][8 * ng + 4]);
                float av[8] = {q0.x, q0.y, q0.z, q0.w, q1.x, q1.y, q1.z, q1.w};
                float bv[4] = {b.x, b.y, b.z, b.w};
#pragma unroll
                for (int i = 0; i < 8; i++)
#pragma unroll
                    for (int c = 0; c < 4; c++) acc[i][c] += av[i] * bv[c];
            }
        }
    }
#pragma unroll
    for (int i = 0; i < 8; i++) {
        int nn = n0 + 8 * ng + i;
        if (nn < NN) {
            float mt = g_mtau[nn], tv = __ldg(tau + nn);
            float4 r;
            float* rr = &r.x;
#pragma unroll
            for (int c = 0; c < 4; c++) {
                int col = 4 * cg + c;
                float o = acc[i][c] + mt * sWl[64 * HID + col] +
                          tv * sWr[64 * HID + col] + sBias[col];
                rr[c] = fmaxf(o, 0.f);
            }
            *(float4*)(g_h1 + (size_t)nn * HID + 4 * cg) = r;
        }
    }
}

// ---------------- layer-2 GEMM + fused FC head ----------------
__global__ __launch_bounds__(256) void gemm2_kernel(
    const float* __restrict__ W2l, const float* __restrict__ b2l,
    const float* __restrict__ W2r, const float* __restrict__ Wfc,
    const float* __restrict__ bfc, float* __restrict__ out) {
    __shared__ __align__(16) float sWl[HID * HID];
    __shared__ __align__(16) float sWr[HID * HID];
    __shared__ float sBias[HID];
    __shared__ float sFc[HID];
    __shared__ __align__(16) float sA[8][136];
    __shared__ float sRed[128];
    int tid = threadIdx.x;
    for (int i = tid; i < HID * HID; i += 256) { sWl[i] = W2l[i]; sWr[i] = W2r[i]; }
    if (tid < HID) { sBias[tid] = b2l[tid]; sFc[tid] = Wfc[tid]; }
    if (tid < 128) sRed[tid] = 0.f;
    int n0 = blockIdx.x * 128;
    int cg = tid & 15, ng = tid >> 4;
    float acc[8][4];
#pragma unroll
    for (int i = 0; i < 8; i++)
#pragma unroll
        for (int c = 0; c < 4; c++) acc[i][c] = 0.f;
    int ldn = n0 + (tid >> 1);
    int ldk = (tid & 1) * 4;
    for (int pass = 0; pass < 2; pass++) {
        const float* __restrict__ A = pass ? (const float*)g_h1 : (const float*)g_mean;
        const float* W = pass ? sWr : sWl;
        for (int kb = 0; kb < HID; kb += 8) {
            __syncthreads();
            float4 v = make_float4(0.f, 0.f, 0.f, 0.f);
            if (ldn < NN) v = *(const float4*)(A + (size_t)ldn * HID + kb + ldk);
            sA[ldk + 0][tid >> 1] = v.x; sA[ldk + 1][tid >> 1] = v.y;
            sA[ldk + 2][tid >> 1] = v.z; sA[ldk + 3][tid >> 1] = v.w;
            __syncthreads();
#pragma unroll
            for (int kk = 0; kk < 8; kk++) {
                float4 b  = *(const float4*)(W + (kb + kk) * HID + 4 * cg);
                float4 q0 = *(const float4*)(&sA[kk][8 * ng]);
                float4 q1 = *(const float4*)(&sA[kk][8 * ng + 4]);
                float av[8] = {q0.x, q0.y, q0.z, q0.w, q1.x, q1.y, q1.z, q1.w};
                float bv[4] = {b.x, b.y, b.z, b.w};
#pragma unroll
                for (int i = 0; i < 8; i++)
#pragma unroll
                    for (int c = 0; c < 4; c++) acc[i][c] += av[i] * bv[c];
            }
        }
    }
    float bias0 = __ldg(bfc);
#pragma unroll
    for (int i = 0; i < 8; i++) {
        float p = 0.f;
#pragma unroll
        for (int c = 0; c < 4; c++) {
            int col = 4 * cg + c;
            float h = fmaxf(acc[i][c] + sBias[col], 0.f);
            p += h * sFc[col];
        }
        atomicAdd(&sRed[8 * ng + i], p);
    }
    __syncthreads();
    if (tid < 128) {
        int nn = n0 + tid;
        if (nn < NN) out[nn] = sRed[tid] + bias0;
    }
}

// ---------------- launch ----------------
extern "C" void kernel_launch(void* const* d_in, const int* in_sizes, int n_in,
                              void* d_out, int out_size) {
    const float* x    = (const float*)d_in[0];
    const void*  ei   = d_in[1];
    const float* tau  = (const float*)d_in[2];
    const float* W1l  = (const float*)d_in[3];
    const float* b1l  = (const float*)d_in[4];
    const float* W1r  = (const float*)d_in[5];
    const float* W2l  = (const float*)d_in[6];
    const float* b2l  = (const float*)d_in[7];
    const float* W2r  = (const float*)d_in[8];
    const float* Wfc  = (const float*)d_in[9];
    const float* bfc  = (const float*)d_in[10];
    float*       out  = (float*)d_out;

    detect_kernel<<<1, 32>>>((const long long*)ei);
    zero_cnt_kernel<<<(NN + 255) / 256, 256>>>();
    deg_kernel<<<(NE + 255) / 256, 256>>>(ei);
    scan_kernel<<<1, 1024>>>();
    fill_kernel<<<(NE + 255) / 256, 256>>>(ei);

    // layer 1
    agg_kernel<true><<<(NN * 32 + 255) / 256, 256>>>(x, tau);
    gemm1_kernel<<<(NN + 127) / 128, 256>>>(x, tau, W1l, b1l, W1r);

    // layer 2 (+ fused FC head)
    agg_kernel<false><<<(NN * 32 + 255) / 256, 256>>>(x, tau);
    gemm2_kernel<<<(NN + 127) / 128, 256>>>(W2l, b2l, W2r, Wfc, bfc, out);
}

// round 6
// speedup vs baseline: 1.1895x; 1.1895x over previous
#include <cuda_runtime.h>

#define NN 100000
#define NE 3200000
#define HID 64
#define NBLK ((NN + 1023) / 1024)   // 98 scan blocks

// ---------------- scratch (device globals; no allocation) ----------------
__device__ int   g_is64;
__device__ int   g_cnt[NN];
__device__ int   g_off[NN + 1];
__device__ int   g_off2[NN];
__device__ int   g_bsum[NBLK];
__device__ int   g_boff[NBLK];
__device__ int   g_csr[NE];
__device__ float g_mean[(size_t)NN * HID];
__device__ float g_mtau[NN];
__device__ float g_h1[(size_t)NN * HID];

// ---------------- edge-index dtype detection ----------------
// Reference requests int64 but JAX default config downcasts to int32.
// Genuine int64 node ids are always in [0, NN); int32 data misread as int64
// has a random node id in the high word -> out of range almost surely.
__global__ void detect_kernel(const long long* __restrict__ ei) {
    int lane = threadIdx.x;
    int ok = 1;
    for (int i = lane; i < 4096; i += 32) {
        long long v = ei[i];
        if (v < 0 || v >= NN) ok = 0;
    }
    unsigned b = __ballot_sync(0xffffffffu, ok);
    if (lane == 0) g_is64 = (b == 0xffffffffu) ? 1 : 0;
}

__device__ __forceinline__ int edge_at(const void* eiv, long long idx) {
    if (g_is64) return (int)((const long long*)eiv)[idx];
    return ((const int*)eiv)[idx];
}

// ---------------- CSR build ----------------
__global__ void zero_cnt_kernel() {
    int i = blockIdx.x * blockDim.x + threadIdx.x;
    if (i < NN) g_cnt[i] = 0;
}

__global__ void deg_kernel(const void* __restrict__ eiv) {
    int e = blockIdx.x * blockDim.x + threadIdx.x;
    if (e < NE) {
        int dst = edge_at(eiv, (long long)NE + e);
        if ((unsigned)dst < NN) atomicAdd(&g_cnt[dst], 1);
    }
}

// ---- two-level scan: block sums -> scan of sums -> per-block scan ----
__global__ void bsum_kernel() {
    __shared__ int wsum[32];
    int tid = threadIdx.x, lane = tid & 31, w = tid >> 5;
    int i = blockIdx.x * 1024 + tid;
    int v = (i < NN) ? g_cnt[i] : 0;
#pragma unroll
    for (int d = 16; d; d >>= 1) v += __shfl_xor_sync(0xffffffffu, v, d);
    if (lane == 0) wsum[w] = v;
    __syncthreads();
    if (w == 0) {
        int s = wsum[lane];
#pragma unroll
        for (int d = 16; d; d >>= 1) s += __shfl_xor_sync(0xffffffffu, s, d);
        if (lane == 0) g_bsum[blockIdx.x] = s;
    }
}

__global__ void bscan_kernel() {
    // single 128-thread-block exclusive scan of NBLK (<=128) block sums
    __shared__ int wsum[4];
    int tid = threadIdx.x, lane = tid & 31, w = tid >> 5;
    int v = (tid < NBLK) ? g_bsum[tid] : 0;
    int xv = v;
#pragma unroll
    for (int d = 1; d < 32; d <<= 1) {
        int y = __shfl_up_sync(0xffffffffu, xv, d);
        if (lane >= d) xv += y;
    }
    if (lane == 31) wsum[w] = xv;
    __syncthreads();
    int carry = 0;
#pragma unroll
    for (int ww = 0; ww < 4; ww++) {
        if (ww < w) carry += wsum[ww];
    }
    int incl = xv + carry;
    if (tid < NBLK) g_boff[tid] = incl - v;
    if (tid == 127) g_off[NN] = incl;
}

__global__ void scan2_kernel() {
    __shared__ int wsum[32];
    int tid = threadIdx.x, lane = tid & 31, w = tid >> 5;
    int i = blockIdx.x * 1024 + tid;
    int v = (i < NN) ? g_cnt[i] : 0;
    int xv = v;
#pragma unroll
    for (int d = 1; d < 32; d <<= 1) {
        int y = __shfl_up_sync(0xffffffffu, xv, d);
        if (lane >= d) xv += y;
    }
    if (lane == 31) wsum[w] = xv;
    __syncthreads();
    if (w == 0) {
        int s = wsum[lane];
#pragma unroll
        for (int d = 1; d < 32; d <<= 1) {
            int y = __shfl_up_sync(0xffffffffu, s, d);
            if (lane >= d) s += y;
        }
        wsum[lane] = s;
    }
    __syncthreads();
    int excl = xv - v + (w ? wsum[w - 1] : 0) + g_boff[blockIdx.x];
    if (i < NN) { g_off[i] = excl; g_off2[i] = excl; }
}

__global__ void fill_kernel(const void* __restrict__ eiv) {
    int e = blockIdx.x * blockDim.x + threadIdx.x;
    if (e < NE) {
        int src = edge_at(eiv, e);
        int dst = edge_at(eiv, (long long)NE + e);
        if ((unsigned)dst < NN && (unsigned)src < NN) {
            int p = atomicAdd(&g_off2[dst], 1);
            if ((unsigned)p < NE) g_csr[p] = src;
        }
    }
}

// ---------------- aggregation: warp per node, mean of 64-dim rows (+tau) ----------------
template <bool TAU>
__global__ void agg_kernel(const float* __restrict__ featp,
                           const float* __restrict__ tau) {
    const float* __restrict__ feat = TAU ? featp : (const float*)g_h1;
    int lane = threadIdx.x & 31;
    int n = (blockIdx.x * blockDim.x + threadIdx.x) >> 5;
    if (n >= NN) return;
    int beg = g_off[n], end = g_off[n + 1];
    float a0 = 0.f, a1 = 0.f, at = 0.f;
    int j = beg;
    int nfull = (end - beg) >> 5;
    for (int c = 0; c < nfull; c++, j += 32) {
        int s = g_csr[j + lane];
        if (TAU) at += __ldg(tau + s);
#pragma unroll
        for (int k = 0; k < 32; k++) {
            int si = __shfl_sync(0xffffffffu, s, k);
            float2 v = *(const float2*)(feat + (size_t)si * HID + 2 * lane);
            a0 += v.x; a1 += v.y;
        }
    }
    int rem = end - j;
    if (rem > 0) {
        int s = (lane < rem) ? g_csr[j + lane] : 0;
        if (TAU && lane < rem) at += __ldg(tau + s);
        for (int k = 0; k < rem; k++) {
            int si = __shfl_sync(0xffffffffu, s, k);
            float2 v = *(const float2*)(feat + (size_t)si * HID + 2 * lane);
            a0 += v.x; a1 += v.y;
        }
    }
    float inv = 1.f / fmaxf((float)(end - beg), 1.f);
    float2 o; o.x = a0 * inv; o.y = a1 * inv;
    *(float2*)(g_mean + (size_t)n * HID + 2 * lane) = o;
    if (TAU) {
#pragma unroll
        for (int d = 16; d; d >>= 1) at += __shfl_xor_sync(0xffffffffu, at, d);
        if (lane == 0) g_mtau[n] = at * inv;
    }
}

// ---------------- layer-1 GEMM: h1 = relu(mean@W1l[0:64] + mtau*W1l[64] + x@W1r[0:64] + tau*W1r[64] + b1l) ----------------
__global__ __launch_bounds__(256) void gemm1_kernel(
    const float* __restrict__ x, const float* __restrict__ tau,
    const float* __restrict__ W1l, const float* __restrict__ b1l,
    const float* __restrict__ W1r) {
    __shared__ __align__(16) float sWl[65 * HID];
    __shared__ __align__(16) float sWr[65 * HID];
    __shared__ float sBias[HID];
    __shared__ __align__(16) float sA[8][136];
    int tid = threadIdx.x;
    for (int i = tid; i < 65 * HID; i += 256) { sWl[i] = W1l[i]; sWr[i] = W1r[i]; }
    if (tid < HID) sBias[tid] = b1l[tid];
    int n0 = blockIdx.x * 128;
    int cg = tid & 15, ng = tid >> 4;
    float acc[8][4];
#pragma unroll
    for (int i = 0; i < 8; i++)
#pragma unroll
        for (int c = 0; c < 4; c++) acc[i][c] = 0.f;
    int ldn = n0 + (tid >> 1);
    int ldk = (tid & 1) * 4;
    for (int pass = 0; pass < 2; pass++) {
        const float* __restrict__ A = pass ? x : (const float*)g_mean;
        const float* W = pass ? sWr : sWl;
        for (int kb = 0; kb < HID; kb += 8) {
            __syncthreads();
            float4 v = make_float4(0.f, 0.f, 0.f, 0.f);
            if (ldn < NN) v = *(const float4*)(A + (size_t)ldn * HID + kb + ldk);
            sA[ldk + 0][tid >> 1] = v.x; sA[ldk + 1][tid >> 1] = v.y;
            sA[ldk + 2][tid >> 1] = v.z; sA[ldk + 3][tid >> 1] = v.w;
            __syncthreads();
#pragma unroll
            for (int kk = 0; kk < 8; kk++) {
                float4 b  = *(const float4*)(W + (kb + kk) * HID + 4 * cg);
                float4 q0 = *(const float4*)(&sA[kk][8 * ng]);
                float4 q1 = *(const float4*)(&sA[kk][8 * ng + 4]);
                float av[8] = {q0.x, q0.y, q0.z, q0.w, q1.x, q1.y, q1.z, q1.w};
                float bv[4] = {b.x, b.y, b.z, b.w};
#pragma unroll
                for (int i = 0; i < 8; i++)
#pragma unroll
                    for (int c = 0; c < 4; c++) acc[i][c] += av[i] * bv[c];
            }
        }
    }
#pragma unroll
    for (int i = 0; i < 8; i++) {
        int nn = n0 + 8 * ng + i;
        if (nn < NN) {
            float mt = g_mtau[nn], tv = __ldg(tau + nn);
            float4 r;
            float* rr = &r.x;
#pragma unroll
            for (int c = 0; c < 4; c++) {
                int col = 4 * cg + c;
                float o = acc[i][c] + mt * sWl[64 * HID + col] +
                          tv * sWr[64 * HID + col] + sBias[col];
                rr[c] = fmaxf(o, 0.f);
            }
            *(float4*)(g_h1 + (size_t)nn * HID + 4 * cg) = r;
        }
    }
}

// ---------------- layer-2 GEMM + fused FC head ----------------
__global__ __launch_bounds__(256) void gemm2_kernel(
    const float* __restrict__ W2l, const float* __restrict__ b2l,
    const float* __restrict__ W2r, const float* __restrict__ Wfc,
    const float* __restrict__ bfc, float* __restrict__ out) {
    __shared__ __align__(16) float sWl[HID * HID];
    __shared__ __align__(16) float sWr[HID * HID];
    __shared__ float sBias[HID];
    __shared__ float sFc[HID];
    __shared__ __align__(16) float sA[8][136];
    __shared__ float sRed[128];
    int tid = threadIdx.x;
    for (int i = tid; i < HID * HID; i += 256) { sWl[i] = W2l[i]; sWr[i] = W2r[i]; }
    if (tid < HID) { sBias[tid] = b2l[tid]; sFc[tid] = Wfc[tid]; }
    if (tid < 128) sRed[tid] = 0.f;
    int n0 = blockIdx.x * 128;
    int cg = tid & 15, ng = tid >> 4;
    float acc[8][4];
#pragma unroll
    for (int i = 0; i < 8; i++)
#pragma unroll
        for (int c = 0; c < 4; c++) acc[i][c] = 0.f;
    int ldn = n0 + (tid >> 1);
    int ldk = (tid & 1) * 4;
    for (int pass = 0; pass < 2; pass++) {
        const float* __restrict__ A = pass ? (const float*)g_h1 : (const float*)g_mean;
        const float* W = pass ? sWr : sWl;
        for (int kb = 0; kb < HID; kb += 8) {
            __syncthreads();
            float4 v = make_float4(0.f, 0.f, 0.f, 0.f);
            if (ldn < NN) v = *(const float4*)(A + (size_t)ldn * HID + kb + ldk);
            sA[ldk + 0][tid >> 1] = v.x; sA[ldk + 1][tid >> 1] = v.y;
            sA[ldk + 2][tid >> 1] = v.z; sA[ldk + 3][tid >> 1] = v.w;
            __syncthreads();
#pragma unroll
            for (int kk = 0; kk < 8; kk++) {
                float4 b  = *(const float4*)(W + (kb + kk) * HID + 4 * cg);
                float4 q0 = *(const float4*)(&sA[kk][8 * ng]);
                float4 q1 = *(const float4*)(&sA[kk][8 * ng + 4]);
                float av[8] = {q0.x, q0.y, q0.z, q0.w, q1.x, q1.y, q1.z, q1.w};
                float bv[4] = {b.x, b.y, b.z, b.w};
#pragma unroll
                for (int i = 0; i < 8; i++)
#pragma unroll
                    for (int c = 0; c < 4; c++) acc[i][c] += av[i] * bv[c];
            }
        }
    }
    float bias0 = __ldg(bfc);
#pragma unroll
    for (int i = 0; i < 8; i++) {
        float p = 0.f;
#pragma unroll
        for (int c = 0; c < 4; c++) {
            int col = 4 * cg + c;
            float h = fmaxf(acc[i][c] + sBias[col], 0.f);
            p += h * sFc[col];
        }
        atomicAdd(&sRed[8 * ng + i], p);
    }
    __syncthreads();
    if (tid < 128) {
        int nn = n0 + tid;
        if (nn < NN) out[nn] = sRed[tid] + bias0;
    }
}

// ---------------- launch ----------------
extern "C" void kernel_launch(void* const* d_in, const int* in_sizes, int n_in,
                              void* d_out, int out_size) {
    const float* x    = (const float*)d_in[0];
    const void*  ei   = d_in[1];
    const float* tau  = (const float*)d_in[2];
    const float* W1l  = (const float*)d_in[3];
    const float* b1l  = (const float*)d_in[4];
    const float* W1r  = (const float*)d_in[5];
    const float* W2l  = (const float*)d_in[6];
    const float* b2l  = (const float*)d_in[7];
    const float* W2r  = (const float*)d_in[8];
    const float* Wfc  = (const float*)d_in[9];
    const float* bfc  = (const float*)d_in[10];
    float*       out  = (float*)d_out;

    detect_kernel<<<1, 32>>>((const long long*)ei);
    zero_cnt_kernel<<<(NN + 255) / 256, 256>>>();
    deg_kernel<<<(NE + 255) / 256, 256>>>(ei);
    bsum_kernel<<<NBLK, 1024>>>();
    bscan_kernel<<<1, 128>>>();
    scan2_kernel<<<NBLK, 1024>>>();
    fill_kernel<<<(NE + 255) / 256, 256>>>(ei);

    // layer 1
    agg_kernel<true><<<(NN * 32 + 255) / 256, 256>>>(x, tau);
    gemm1_kernel<<<(NN + 127) / 128, 256>>>(x, tau, W1l, b1l, W1r);

    // layer 2 (+ fused FC head)
    agg_kernel<false><<<(NN * 32 + 255) / 256, 256>>>(x, tau);
    gemm2_kernel<<<(NN + 127) / 128, 256>>>(W2l, b2l, W2r, Wfc, bfc, out);
}

// round 11
// speedup vs baseline: 1.2029x; 1.0113x over previous
#include <cuda_runtime.h>

#define NN 100000
#define NE 3200000
#define HID 64
#define NBLK ((NN + 1023) / 1024)   // 98 scan blocks

// ---------------- scratch (device globals; no allocation) ----------------
__device__ int   g_is64;
__device__ int   g_cnt[NN];
__device__ int   g_off[NN + 1];
__device__ int   g_off2[NN];
__device__ int   g_bsum[NBLK];
__device__ int   g_boff[NBLK];
__device__ int   g_csr[NE];
__device__ float g_mean[(size_t)NN * HID];
__device__ float g_mtau[NN];
__device__ float g_h1[(size_t)NN * HID];

// ---------------- packed f32x2 helpers (FFMA2 — PTX-only, 2x fp32 fma rate) ----
__device__ __forceinline__ unsigned long long pack2(float lo, float hi) {
    unsigned long long r;
    asm("mov.b64 %0, {%1, %2};" : "=l"(r) : "f"(lo), "f"(hi));
    return r;
}
__device__ __forceinline__ void fma2(unsigned long long& d,
                                     unsigned long long a,
                                     unsigned long long b) {
    asm("fma.rn.f32x2 %0, %1, %2, %0;" : "+l"(d) : "l"(a), "l"(b));
}
__device__ __forceinline__ float2 unpack2(unsigned long long v) {
    float2 f;
    asm("mov.b64 {%0, %1}, %2;" : "=f"(f.x), "=f"(f.y) : "l"(v));
    return f;
}

// ---------------- edge-index dtype detection ----------------
// Reference requests int64 but JAX default config downcasts to int32.
// Genuine int64 node ids are always in [0, NN); int32 data misread as int64
// has a random node id in the high word -> out of range almost surely.
__global__ void detect_kernel(const long long* __restrict__ ei) {
    int lane = threadIdx.x;
    int ok = 1;
    for (int i = lane; i < 4096; i += 32) {
        long long v = ei[i];
        if (v < 0 || v >= NN) ok = 0;
    }
    unsigned b = __ballot_sync(0xffffffffu, ok);
    if (lane == 0) g_is64 = (b == 0xffffffffu) ? 1 : 0;
}

__device__ __forceinline__ int edge_at(const void* eiv, long long idx) {
    if (g_is64) return (int)((const long long*)eiv)[idx];
    return ((const int*)eiv)[idx];
}

// ---------------- CSR build ----------------
__global__ void zero_cnt_kernel() {
    int i = blockIdx.x * blockDim.x + threadIdx.x;
    if (i < NN) g_cnt[i] = 0;
}

__global__ void deg_kernel(const void* __restrict__ eiv) {
    int e = blockIdx.x * blockDim.x + threadIdx.x;
    if (e < NE) {
        int dst = edge_at(eiv, (long long)NE + e);
        if ((unsigned)dst < NN) atomicAdd(&g_cnt[dst], 1);
    }
}

// ---- two-level scan: block sums -> scan of sums -> per-block scan ----
__global__ void bsum_kernel() {
    __shared__ int wsum[32];
    int tid = threadIdx.x, lane = tid & 31, w = tid >> 5;
    int i = blockIdx.x * 1024 + tid;
    int v = (i < NN) ? g_cnt[i] : 0;
#pragma unroll
    for (int d = 16; d; d >>= 1) v += __shfl_xor_sync(0xffffffffu, v, d);
    if (lane == 0) wsum[w] = v;
    __syncthreads();
    if (w == 0) {
        int s = wsum[lane];
#pragma unroll
        for (int d = 16; d; d >>= 1) s += __shfl_xor_sync(0xffffffffu, s, d);
        if (lane == 0) g_bsum[blockIdx.x] = s;
    }
}

__global__ void bscan_kernel() {
    // single 128-thread-block exclusive scan of NBLK (<=128) block sums
    __shared__ int wsum[4];
    int tid = threadIdx.x, lane = tid & 31, w = tid >> 5;
    int v = (tid < NBLK) ? g_bsum[tid] : 0;
    int xv = v;
#pragma unroll
    for (int d = 1; d < 32; d <<= 1) {
        int y = __shfl_up_sync(0xffffffffu, xv, d);
        if (lane >= d) xv += y;
    }
    if (lane == 31) wsum[w] = xv;
    __syncthreads();
    int carry = 0;
#pragma unroll
    for (int ww = 0; ww < 4; ww++) {
        if (ww < w) carry += wsum[ww];
    }
    int incl = xv + carry;
    if (tid < NBLK) g_boff[tid] = incl - v;
    if (tid == 127) g_off[NN] = incl;
}

__global__ void scan2_kernel() {
    __shared__ int wsum[32];
    int tid = threadIdx.x, lane = tid & 31, w = tid >> 5;
    int i = blockIdx.x * 1024 + tid;
    int v = (i < NN) ? g_cnt[i] : 0;
    int xv = v;
#pragma unroll
    for (int d = 1; d < 32; d <<= 1) {
        int y = __shfl_up_sync(0xffffffffu, xv, d);
        if (lane >= d) xv += y;
    }
    if (lane == 31) wsum[w] = xv;
    __syncthreads();
    if (w == 0) {
        int s = wsum[lane];
#pragma unroll
        for (int d = 1; d < 32; d <<= 1) {
            int y = __shfl_up_sync(0xffffffffu, s, d);
            if (lane >= d) s += y;
        }
        wsum[lane] = s;
    }
    __syncthreads();
    int excl = xv - v + (w ? wsum[w - 1] : 0) + g_boff[blockIdx.x];
    if (i < NN) { g_off[i] = excl; g_off2[i] = excl; }
}

__global__ void fill_kernel(const void* __restrict__ eiv) {
    int e = blockIdx.x * blockDim.x + threadIdx.x;
    if (e < NE) {
        int src = edge_at(eiv, e);
        int dst = edge_at(eiv, (long long)NE + e);
        if ((unsigned)dst < NN && (unsigned)src < NN) {
            int p = atomicAdd(&g_off2[dst], 1);
            if ((unsigned)p < NE) g_csr[p] = src;
        }
    }
}

// ---------------- aggregation: warp per node, mean of 64-dim rows (+tau) ----------------
template <bool TAU>
__global__ void agg_kernel(const float* __restrict__ featp,
                           const float* __restrict__ tau) {
    const float* __restrict__ feat = TAU ? featp : (const float*)g_h1;
    int lane = threadIdx.x & 31;
    int n = (blockIdx.x * blockDim.x + threadIdx.x) >> 5;
    if (n >= NN) return;
    int beg = g_off[n], end = g_off[n + 1];
    float a0 = 0.f, a1 = 0.f, at = 0.f;
    int j = beg;
    int nfull = (end - beg) >> 5;
    for (int c = 0; c < nfull; c++, j += 32) {
        int s = g_csr[j + lane];
        if (TAU) at += __ldg(tau + s);
#pragma unroll
        for (int k = 0; k < 32; k++) {
            int si = __shfl_sync(0xffffffffu, s, k);
            float2 v = *(const float2*)(feat + (size_t)si * HID + 2 * lane);
            a0 += v.x; a1 += v.y;
        }
    }
    int rem = end - j;
    if (rem > 0) {
        int s = (lane < rem) ? g_csr[j + lane] : 0;
        if (TAU && lane < rem) at += __ldg(tau + s);
        for (int k = 0; k < rem; k++) {
            int si = __shfl_sync(0xffffffffu, s, k);
            float2 v = *(const float2*)(feat + (size_t)si * HID + 2 * lane);
            a0 += v.x; a1 += v.y;
        }
    }
    float inv = 1.f / fmaxf((float)(end - beg), 1.f);
    float2 o; o.x = a0 * inv; o.y = a1 * inv;
    *(float2*)(g_mean + (size_t)n * HID + 2 * lane) = o;
    if (TAU) {
#pragma unroll
        for (int d = 16; d; d >>= 1) at += __shfl_xor_sync(0xffffffffu, at, d);
        if (lane == 0) g_mtau[n] = at * inv;
    }
}

// ---------------- layer-1 GEMM: h1 = relu(mean@W1l[0:64] + mtau*W1l[64] + x@W1r[0:64] + tau*W1r[64] + b1l) ----------------
__global__ __launch_bounds__(256) void gemm1_kernel(
    const float* __restrict__ x, const float* __restrict__ tau,
    const float* __restrict__ W1l, const float* __restrict__ b1l,
    const float* __restrict__ W1r) {
    __shared__ __align__(16) float sWl[65 * HID];
    __shared__ __align__(16) float sWr[65 * HID];
    __shared__ float sBias[HID];
    __shared__ __align__(16) float sA[8][136];
    int tid = threadIdx.x;
    for (int i = tid; i < 65 * HID; i += 256) { sWl[i] = W1l[i]; sWr[i] = W1r[i]; }
    if (tid < HID) sBias[tid] = b1l[tid];
    int n0 = blockIdx.x * 128;
    int cg = tid & 15, ng = tid >> 4;
    // acc2[i][q] packs output cols (2q, 2q+1) for row i as f32x2
    unsigned long long acc2[8][2];
#pragma unroll
    for (int i = 0; i < 8; i++) { acc2[i][0] = 0ull; acc2[i][1] = 0ull; }
    int ldn = n0 + (tid >> 1);
    int ldk = (tid & 1) * 4;
    for (int pass = 0; pass < 2; pass++) {
        const float* __restrict__ A = pass ? x : (const float*)g_mean;
        const float* W = pass ? sWr : sWl;
        for (int kb = 0; kb < HID; kb += 8) {
            __syncthreads();
            float4 v = make_float4(0.f, 0.f, 0.f, 0.f);
            if (ldn < NN) v = *(const float4*)(A + (size_t)ldn * HID + kb + ldk);
            sA[ldk + 0][tid >> 1] = v.x; sA[ldk + 1][tid >> 1] = v.y;
            sA[ldk + 2][tid >> 1] = v.z; sA[ldk + 3][tid >> 1] = v.w;
            __syncthreads();
#pragma unroll
            for (int kk = 0; kk < 8; kk++) {
                float4 b  = *(const float4*)(W + (kb + kk) * HID + 4 * cg);
                float4 q0 = *(const float4*)(&sA[kk][8 * ng]);
                float4 q1 = *(const float4*)(&sA[kk][8 * ng + 4]);
                unsigned long long bp0 = pack2(b.x, b.y);
                unsigned long long bp1 = pack2(b.z, b.w);
                float av[8] = {q0.x, q0.y, q0.z, q0.w, q1.x, q1.y, q1.z, q1.w};
#pragma unroll
                for (int i = 0; i < 8; i++) {
                    unsigned long long ad = pack2(av[i], av[i]);
                    fma2(acc2[i][0], ad, bp0);
                    fma2(acc2[i][1], ad, bp1);
                }
            }
        }
    }
#pragma unroll
    for (int i = 0; i < 8; i++) {
        int nn = n0 + 8 * ng + i;
        if (nn < NN) {
            float mt = g_mtau[nn], tv = __ldg(tau + nn);
            float2 p0 = unpack2(acc2[i][0]);
            float2 p1 = unpack2(acc2[i][1]);
            float accv[4] = {p0.x, p0.y, p1.x, p1.y};
            float4 r;
            float* rr = &r.x;
#pragma unroll
            for (int c = 0; c < 4; c++) {
                int col = 4 * cg + c;
                float o = accv[c] + mt * sWl[64 * HID + col] +
                          tv * sWr[64 * HID + col] + sBias[col];
                rr[c] = fmaxf(o, 0.f);
            }
            *(float4*)(g_h1 + (size_t)nn * HID + 4 * cg) = r;
        }
    }
}

// ---------------- layer-2 GEMM + fused FC head ----------------
__global__ __launch_bounds__(256) void gemm2_kernel(
    const float* __restrict__ W2l, const float* __restrict__ b2l,
    const float* __restrict__ W2r, const float* __restrict__ Wfc,
    const float* __restrict__ bfc, float* __restrict__ out) {
    __shared__ __align__(16) float sWl[HID * HID];
    __shared__ __align__(16) float sWr[HID * HID];
    __shared__ float sBias[HID];
    __shared__ float sFc[HID];
    __shared__ __align__(16) float sA[8][136];
    __shared__ float sRed[128];
    int tid = threadIdx.x;
    for (int i = tid; i < HID * HID; i += 256) { sWl[i] = W2l[i]; sWr[i] = W2r[i]; }
    if (tid < HID) { sBias[tid] = b2l[tid]; sFc[tid] = Wfc[tid]; }
    if (tid < 128) sRed[tid] = 0.f;
    int n0 = blockIdx.x * 128;
    int cg = tid & 15, ng = tid >> 4;
    unsigned long long acc2[8][2];
#pragma unroll
    for (int i = 0; i < 8; i++) { acc2[i][0] = 0ull; acc2[i][1] = 0ull; }
    int ldn = n0 + (tid >> 1);
    int ldk = (tid & 1) * 4;
    for (int pass = 0; pass < 2; pass++) {
        const float* __restrict__ A = pass ? (const float*)g_h1 : (const float*)g_mean;
        const float* W = pass ? sWr : sWl;
        for (int kb = 0; kb < HID; kb += 8) {
            __syncthreads();
            float4 v = make_float4(0.f, 0.f, 0.f, 0.f);
            if (ldn < NN) v = *(const float4*)(A + (size_t)ldn * HID + kb + ldk);
            sA[ldk + 0][tid >> 1] = v.x; sA[ldk + 1][tid >> 1] = v.y;
            sA[ldk + 2][tid >> 1] = v.z; sA[ldk + 3][tid >> 1] = v.w;
            __syncthreads();
#pragma unroll
            for (int kk = 0; kk < 8; kk++) {
                float4 b  = *(const float4*)(W + (kb + kk) * HID + 4 * cg);
                float4 q0 = *(const float4*)(&sA[kk][8 * ng]);
                float4 q1 = *(const float4*)(&sA[kk][8 * ng + 4]);
                unsigned long long bp0 = pack2(b.x, b.y);
                unsigned long long bp1 = pack2(b.z, b.w);
                float av[8] = {q0.x, q0.y, q0.z, q0.w, q1.x, q1.y, q1.z, q1.w};
#pragma unroll
                for (int i = 0; i < 8; i++) {
                    unsigned long long ad = pack2(av[i], av[i]);
                    fma2(acc2[i][0], ad, bp0);
                    fma2(acc2[i][1], ad, bp1);
                }
            }
        }
    }
    float bias0 = __ldg(bfc);
#pragma unroll
    for (int i = 0; i < 8; i++) {
        float2 p0 = unpack2(acc2[i][0]);
        float2 p1 = unpack2(acc2[i][1]);
        float accv[4] = {p0.x, p0.y, p1.x, p1.y};
        float p = 0.f;
#pragma unroll
        for (int c = 0; c < 4; c++) {
            int col = 4 * cg + c;
            float h = fmaxf(accv[c] + sBias[col], 0.f);
            p += h * sFc[col];
        }
        atomicAdd(&sRed[8 * ng + i], p);
    }
    __syncthreads();
    if (tid < 128) {
        int nn = n0 + tid;
        if (nn < NN) out[nn] = sRed[tid] + bias0;
    }
}

// ---------------- launch ----------------
extern "C" void kernel_launch(void* const* d_in, const int* in_sizes, int n_in,
                              void* d_out, int out_size) {
    const float* x    = (const float*)d_in[0];
    const void*  ei   = d_in[1];
    const float* tau  = (const float*)d_in[2];
    const float* W1l  = (const float*)d_in[3];
    const float* b1l  = (const float*)d_in[4];
    const float* W1r  = (const float*)d_in[5];
    const float* W2l  = (const float*)d_in[6];
    const float* b2l  = (const float*)d_in[7];
    const float* W2r  = (const float*)d_in[8];
    const float* Wfc  = (const float*)d_in[9];
    const float* bfc  = (const float*)d_in[10];
    float*       out  = (float*)d_out;

    detect_kernel<<<1, 32>>>((const long long*)ei);
    zero_cnt_kernel<<<(NN + 255) / 256, 256>>>();
    deg_kernel<<<(NE + 255) / 256, 256>>>(ei);
    bsum_kernel<<<NBLK, 1024>>>();
    bscan_kernel<<<1, 128>>>();
    scan2_kernel<<<NBLK, 1024>>>();
    fill_kernel<<<(NE + 255) / 256, 256>>>(ei);

    // layer 1
    agg_kernel<true><<<(NN * 32 + 255) / 256, 256>>>(x, tau);
    gemm1_kernel<<<(NN + 127) / 128, 256>>>(x, tau, W1l, b1l, W1r);

    // layer 2 (+ fused FC head)
    agg_kernel<false><<<(NN * 32 + 255) / 256, 256>>>(x, tau);
    gemm2_kernel<<<(NN + 127) / 128, 256>>>(W2l, b2l, W2r, Wfc, bfc, out);
}

// round 12
// speedup vs baseline: 1.2082x; 1.0044x over previous
#include <cuda_runtime.h>

#define NN 100000
#define NE 3200000
#define HID 64
#define NBLK ((NN + 1023) / 1024)   // 98 scan blocks

// ---------------- scratch (device globals; no allocation) ----------------
__device__ int   g_is64;
__device__ int   g_cnt[NN];
__device__ int   g_off[NN + 1];
__device__ int   g_off2[NN];
__device__ unsigned long long g_desc[NBLK];  // (sum<<2)|flag; 0=invalid 1=partial 2=prefix
__device__ int   g_blkctr;
__device__ int   g_csr[NE];
__device__ float g_mean[(size_t)NN * HID];
__device__ float g_mtau[NN];
__device__ float g_h1[(size_t)NN * HID];

// ---------------- packed f32x2 helpers (FFMA2 — PTX-only, 2x fp32 fma rate) ----
__device__ __forceinline__ unsigned long long pack2(float lo, float hi) {
    unsigned long long r;
    asm("mov.b64 %0, {%1, %2};" : "=l"(r) : "f"(lo), "f"(hi));
    return r;
}
__device__ __forceinline__ void fma2(unsigned long long& d,
                                     unsigned long long a,
                                     unsigned long long b) {
    asm("fma.rn.f32x2 %0, %1, %2, %0;" : "+l"(d) : "l"(a), "l"(b));
}
__device__ __forceinline__ float2 unpack2(unsigned long long v) {
    float2 f;
    asm("mov.b64 {%0, %1}, %2;" : "=f"(f.x), "=f"(f.y) : "l"(v));
    return f;
}

// ---------------- init: zero counters/flags + edge dtype detection ----------------
// Reference requests int64 but JAX default config downcasts to int32.
// Genuine int64 node ids are always in [0, NN); int32 data misread as int64
// has a random node id in the high word -> out of range almost surely.
__global__ void init_kernel(const long long* __restrict__ ei) {
    int i = blockIdx.x * blockDim.x + threadIdx.x;
    if (i < NN) g_cnt[i] = 0;
    if (i < NBLK) g_desc[i] = 0ull;
    if (i == NN) g_blkctr = 0;
    if (blockIdx.x == 0 && threadIdx.x < 32) {
        int lane = threadIdx.x;
        int ok = 1;
        for (int k = lane; k < 4096; k += 32) {
            long long v = ei[k];
            if (v < 0 || v >= NN) ok = 0;
        }
        unsigned b = __ballot_sync(0xffffffffu, ok);
        if (lane == 0) g_is64 = (b == 0xffffffffu) ? 1 : 0;
    }
}

__device__ __forceinline__ int edge_at(const void* eiv, long long idx) {
    if (g_is64) return (int)((const long long*)eiv)[idx];
    return ((const int*)eiv)[idx];
}

__global__ void deg_kernel(const void* __restrict__ eiv) {
    int e = blockIdx.x * blockDim.x + threadIdx.x;
    if (e < NE) {
        int dst = edge_at(eiv, (long long)NE + e);
        if ((unsigned)dst < NN) atomicAdd(&g_cnt[dst], 1);
    }
}

// ---- single-pass decoupled-lookback exclusive scan: g_cnt -> g_off/g_off2 ----
__global__ void scan_lb_kernel() {
    __shared__ int wsum[32];
    __shared__ int s_bid;
    __shared__ int s_prefix;
    int tid = threadIdx.x, lane = tid & 31, w = tid >> 5;
    if (tid == 0) s_bid = atomicAdd(&g_blkctr, 1);
    __syncthreads();
    int b = s_bid;
    int i = b * 1024 + tid;
    int v = (i < NN) ? g_cnt[i] : 0;
    // block-wide inclusive scan
    int xv = v;
#pragma unroll
    for (int d = 1; d < 32; d <<= 1) {
        int y = __shfl_up_sync(0xffffffffu, xv, d);
        if (lane >= d) xv += y;
    }
    if (lane == 31) wsum[w] = xv;
    __syncthreads();
    if (w == 0) {
        int s = wsum[lane];
#pragma unroll
        for (int d = 1; d < 32; d <<= 1) {
            int y = __shfl_up_sync(0xffffffffu, s, d);
            if (lane >= d) s += y;
        }
        wsum[lane] = s;
    }
    __syncthreads();
    int incl = xv + (w ? wsum[w - 1] : 0);   // block-inclusive
    int btotal = wsum[31];
    // publish partial (or final prefix for block 0)
    if (tid == 0) {
        unsigned long long d = ((unsigned long long)btotal << 2) | (b == 0 ? 2ull : 1ull);
        atomicExch(&g_desc[b], d);
    }
    // lookback (thread 0 only)
    if (tid == 0) {
        if (b == 0) {
            s_prefix = 0;
        } else {
            long long pref = 0;
            int p = b - 1;
            while (true) {
                unsigned long long d;
                do { d = atomicAdd(&g_desc[p], 0ull); } while ((d & 3ull) == 0ull);
                pref += (long long)(d >> 2);
                if ((d & 3ull) == 2ull) break;
                p--;
            }
            s_prefix = (int)pref;
        }
    }
    __syncthreads();
    int prefix = s_prefix;
    if (b > 0 && tid == 0) {
        unsigned long long d = ((unsigned long long)(prefix + btotal) << 2) | 2ull;
        atomicExch(&g_desc[b], d);
    }
    int excl = prefix + incl - v;
    if (i < NN) { g_off[i] = excl; g_off2[i] = excl; }
    if (b == NBLK - 1 && tid == 1023) g_off[NN] = prefix + btotal;
}

__global__ void fill_kernel(const void* __restrict__ eiv) {
    int e = blockIdx.x * blockDim.x + threadIdx.x;
    if (e < NE) {
        int src = edge_at(eiv, e);
        int dst = edge_at(eiv, (long long)NE + e);
        if ((unsigned)dst < NN && (unsigned)src < NN) {
            int p = atomicAdd(&g_off2[dst], 1);
            if ((unsigned)p < NE) g_csr[p] = src;
        }
    }
}

// ---------------- aggregation: warp per node, mean of 64-dim rows (+tau) ----------------
template <bool TAU>
__global__ void agg_kernel(const float* __restrict__ featp,
                           const float* __restrict__ tau) {
    const float* __restrict__ feat = TAU ? featp : (const float*)g_h1;
    int lane = threadIdx.x & 31;
    int n = (blockIdx.x * blockDim.x + threadIdx.x) >> 5;
    if (n >= NN) return;
    int beg = g_off[n], end = g_off[n + 1];
    float a0 = 0.f, a1 = 0.f, at = 0.f;
    int j = beg;
    int nfull = (end - beg) >> 5;
    for (int c = 0; c < nfull; c++, j += 32) {
        int s = g_csr[j + lane];
        if (TAU) at += __ldg(tau + s);
#pragma unroll
        for (int k = 0; k < 32; k++) {
            int si = __shfl_sync(0xffffffffu, s, k);
            float2 v = *(const float2*)(feat + (size_t)si * HID + 2 * lane);
            a0 += v.x; a1 += v.y;
        }
    }
    int rem = end - j;
    if (rem > 0) {
        int s = (lane < rem) ? g_csr[j + lane] : 0;
        if (TAU && lane < rem) at += __ldg(tau + s);
        for (int k = 0; k < rem; k++) {
            int si = __shfl_sync(0xffffffffu, s, k);
            float2 v = *(const float2*)(feat + (size_t)si * HID + 2 * lane);
            a0 += v.x; a1 += v.y;
        }
    }
    float inv = 1.f / fmaxf((float)(end - beg), 1.f);
    float2 o; o.x = a0 * inv; o.y = a1 * inv;
    *(float2*)(g_mean + (size_t)n * HID + 2 * lane) = o;
    if (TAU) {
#pragma unroll
        for (int d = 16; d; d >>= 1) at += __shfl_xor_sync(0xffffffffu, at, d);
        if (lane == 0) g_mtau[n] = at * inv;
    }
}

// ---------------- layer-1 GEMM: h1 = relu(mean@W1l[0:64] + mtau*W1l[64] + x@W1r[0:64] + tau*W1r[64] + b1l) ----------------
__global__ __launch_bounds__(256) void gemm1_kernel(
    const float* __restrict__ x, const float* __restrict__ tau,
    const float* __restrict__ W1l, const float* __restrict__ b1l,
    const float* __restrict__ W1r) {
    __shared__ __align__(16) float sWl[65 * HID];
    __shared__ __align__(16) float sWr[65 * HID];
    __shared__ float sBias[HID];
    __shared__ __align__(16) float sA[8][136];
    int tid = threadIdx.x;
    for (int i = tid; i < 65 * HID; i += 256) { sWl[i] = W1l[i]; sWr[i] = W1r[i]; }
    if (tid < HID) sBias[tid] = b1l[tid];
    int n0 = blockIdx.x * 128;
    int cg = tid & 15, ng = tid >> 4;
    // acc2[i][q] packs output cols (2q, 2q+1) for row i as f32x2
    unsigned long long acc2[8][2];
#pragma unroll
    for (int i = 0; i < 8; i++) { acc2[i][0] = 0ull; acc2[i][1] = 0ull; }
    int ldn = n0 + (tid >> 1);
    int ldk = (tid & 1) * 4;
    for (int pass = 0; pass < 2; pass++) {
        const float* __restrict__ A = pass ? x : (const float*)g_mean;
        const float* W = pass ? sWr : sWl;
        for (int kb = 0; kb < HID; kb += 8) {
            __syncthreads();
            float4 v = make_float4(0.f, 0.f, 0.f, 0.f);
            if (ldn < NN) v = *(const float4*)(A + (size_t)ldn * HID + kb + ldk);
            sA[ldk + 0][tid >> 1] = v.x; sA[ldk + 1][tid >> 1] = v.y;
            sA[ldk + 2][tid >> 1] = v.z; sA[ldk + 3][tid >> 1] = v.w;
            __syncthreads();
#pragma unroll
            for (int kk = 0; kk < 8; kk++) {
                float4 b  = *(const float4*)(W + (kb + kk) * HID + 4 * cg);
                float4 q0 = *(const float4*)(&sA[kk][8 * ng]);
                float4 q1 = *(const float4*)(&sA[kk][8 * ng + 4]);
                unsigned long long bp0 = pack2(b.x, b.y);
                unsigned long long bp1 = pack2(b.z, b.w);
                float av[8] = {q0.x, q0.y, q0.z, q0.w, q1.x, q1.y, q1.z, q1.w};
#pragma unroll
                for (int i = 0; i < 8; i++) {
                    unsigned long long ad = pack2(av[i], av[i]);
                    fma2(acc2[i][0], ad, bp0);
                    fma2(acc2[i][1], ad, bp1);
                }
            }
        }
    }
#pragma unroll
    for (int i = 0; i < 8; i++) {
        int nn = n0 + 8 * ng + i;
        if (nn < NN) {
            float mt = g_mtau[nn], tv = __ldg(tau + nn);
            float2 p0 = unpack2(acc2[i][0]);
            float2 p1 = unpack2(acc2[i][1]);
            float accv[4] = {p0.x, p0.y, p1.x, p1.y};
            float4 r;
            float* rr = &r.x;
#pragma unroll
            for (int c = 0; c < 4; c++) {
                int col = 4 * cg + c;
                float o = accv[c] + mt * sWl[64 * HID + col] +
                          tv * sWr[64 * HID + col] + sBias[col];
                rr[c] = fmaxf(o, 0.f);
            }
            *(float4*)(g_h1 + (size_t)nn * HID + 4 * cg) = r;
        }
    }
}

// ---------------- layer-2 GEMM + fused FC head ----------------
__global__ __launch_bounds__(256) void gemm2_kernel(
    const float* __restrict__ W2l, const float* __restrict__ b2l,
    const float* __restrict__ W2r, const float* __restrict__ Wfc,
    const float* __restrict__ bfc, float* __restrict__ out) {
    __shared__ __align__(16) float sWl[HID * HID];
    __shared__ __align__(16) float sWr[HID * HID];
    __shared__ float sBias[HID];
    __shared__ float sFc[HID];
    __shared__ __align__(16) float sA[8][136];
    __shared__ float sRed[128];
    int tid = threadIdx.x;
    for (int i = tid; i < HID * HID; i += 256) { sWl[i] = W2l[i]; sWr[i] = W2r[i]; }
    if (tid < HID) { sBias[tid] = b2l[tid]; sFc[tid] = Wfc[tid]; }
    if (tid < 128) sRed[tid] = 0.f;
    int n0 = blockIdx.x * 128;
    int cg = tid & 15, ng = tid >> 4;
    unsigned long long acc2[8][2];
#pragma unroll
    for (int i = 0; i < 8; i++) { acc2[i][0] = 0ull; acc2[i][1] = 0ull; }
    int ldn = n0 + (tid >> 1);
    int ldk = (tid & 1) * 4;
    for (int pass = 0; pass < 2; pass++) {
        const float* __restrict__ A = pass ? (const float*)g_h1 : (const float*)g_mean;
        const float* W = pass ? sWr : sWl;
        for (int kb = 0; kb < HID; kb += 8) {
            __syncthreads();
            float4 v = make_float4(0.f, 0.f, 0.f, 0.f);
            if (ldn < NN) v = *(const float4*)(A + (size_t)ldn * HID + kb + ldk);
            sA[ldk + 0][tid >> 1] = v.x; sA[ldk + 1][tid >> 1] = v.y;
            sA[ldk + 2][tid >> 1] = v.z; sA[ldk + 3][tid >> 1] = v.w;
            __syncthreads();
#pragma unroll
            for (int kk = 0; kk < 8; kk++) {
                float4 b  = *(const float4*)(W + (kb + kk) * HID + 4 * cg);
                float4 q0 = *(const float4*)(&sA[kk][8 * ng]);
                float4 q1 = *(const float4*)(&sA[kk][8 * ng + 4]);
                unsigned long long bp0 = pack2(b.x, b.y);
                unsigned long long bp1 = pack2(b.z, b.w);
                float av[8] = {q0.x, q0.y, q0.z, q0.w, q1.x, q1.y, q1.z, q1.w};
#pragma unroll
                for (int i = 0; i < 8; i++) {
                    unsigned long long ad = pack2(av[i], av[i]);
                    fma2(acc2[i][0], ad, bp0);
                    fma2(acc2[i][1], ad, bp1);
                }
            }
        }
    }
    float bias0 = __ldg(bfc);
#pragma unroll
    for (int i = 0; i < 8; i++) {
        float2 p0 = unpack2(acc2[i][0]);
        float2 p1 = unpack2(acc2[i][1]);
        float accv[4] = {p0.x, p0.y, p1.x, p1.y};
        float p = 0.f;
#pragma unroll
        for (int c = 0; c < 4; c++) {
            int col = 4 * cg + c;
            float h = fmaxf(accv[c] + sBias[col], 0.f);
            p += h * sFc[col];
        }
        atomicAdd(&sRed[8 * ng + i], p);
    }
    __syncthreads();
    if (tid < 128) {
        int nn = n0 + tid;
        if (nn < NN) out[nn] = sRed[tid] + bias0;
    }
}

// ---------------- launch ----------------
extern "C" void kernel_launch(void* const* d_in, const int* in_sizes, int n_in,
                              void* d_out, int out_size) {
    const float* x    = (const float*)d_in[0];
    const void*  ei   = d_in[1];
    const float* tau  = (const float*)d_in[2];
    const float* W1l  = (const float*)d_in[3];
    const float* b1l  = (const float*)d_in[4];
    const float* W1r  = (const float*)d_in[5];
    const float* W2l  = (const float*)d_in[6];
    const float* b2l  = (const float*)d_in[7];
    const float* W2r  = (const float*)d_in[8];
    const float* Wfc  = (const float*)d_in[9];
    const float* bfc  = (const float*)d_in[10];
    float*       out  = (float*)d_out;

    init_kernel<<<(NN + 256) / 256, 256>>>((const long long*)ei);
    deg_kernel<<<(NE + 255) / 256, 256>>>(ei);
    scan_lb_kernel<<<NBLK, 1024>>>();
    fill_kernel<<<(NE + 255) / 256, 256>>>(ei);

    // layer 1
    agg_kernel<true><<<(NN * 32 + 255) / 256, 256>>>(x, tau);
    gemm1_kernel<<<(NN + 127) / 128, 256>>>(x, tau, W1l, b1l, W1r);

    // layer 2 (+ fused FC head)
    agg_kernel<false><<<(NN * 32 + 255) / 256, 256>>>(x, tau);
    gemm2_kernel<<<(NN + 127) / 128, 256>>>(W2l, b2l, W2r, Wfc, bfc, out);
}

// round 14
// speedup vs baseline: 1.2602x; 1.0430x over previous
#include <cuda_runtime.h>

#define NN 100000
#define NE 3200000
#define HID 64
#define NBLK ((NN + 1023) / 1024)   // 98 scan blocks

// ---------------- scratch (device globals; no allocation; BSS zero-init) ------
__device__ int      g_cnt[NN];          // zeroed by scan_lb for next call
__device__ int      g_off[NN + 1];
__device__ unsigned g_rank[NE];         // packed dst | (rank<<17)
__device__ unsigned long long g_desc[NBLK];  // (sum<<2)|flag; reset by last block
__device__ int      g_blkctr;           // reset by last block
__device__ int      g_done;             // reset by last block
__device__ int      g_csr[NE];
__device__ float    g_mean[(size_t)NN * HID];
__device__ float    g_mtau[NN];
__device__ float    g_h1[(size_t)NN * HID];

// ---------------- packed f32x2 helpers (FFMA2 — PTX-only, 2x fp32 fma rate) ----
__device__ __forceinline__ unsigned long long pack2(float lo, float hi) {
    unsigned long long r;
    asm("mov.b64 %0, {%1, %2};" : "=l"(r) : "f"(lo), "f"(hi));
    return r;
}
__device__ __forceinline__ void fma2(unsigned long long& d,
                                     unsigned long long a,
                                     unsigned long long b) {
    asm("fma.rn.f32x2 %0, %1, %2, %0;" : "+l"(d) : "l"(a), "l"(b));
}
__device__ __forceinline__ float2 unpack2(unsigned long long v) {
    float2 f;
    asm("mov.b64 {%0, %1}, %2;" : "=f"(f.x), "=f"(f.y) : "l"(v));
    return f;
}

// ---------------- degree + per-edge rank ----------------
// Edge buffer is int32 (proven: int64 interpretation of ei[NE+e] trapped OOB in R1;
// int32 path passes). Rank packs into bits [17:32) — max degree ~70 << 32768.
__global__ void deg_kernel(const int* __restrict__ ei) {
    int e = blockIdx.x * blockDim.x + threadIdx.x;
    if (e < NE) {
        int dst = ei[NE + e];
        unsigned pk = 0xFFFFFFFFu;   // invalid marker (dst field >= NN)
        if ((unsigned)dst < NN) {
            int r = atomicAdd(&g_cnt[dst], 1);
            if (r > 32766) r = 32766;
            pk = (unsigned)dst | ((unsigned)r << 17);
        }
        g_rank[e] = pk;
    }
}

// ---- single-pass decoupled-lookback exclusive scan: g_cnt -> g_off ----
// Also self-cleans g_cnt/g_desc/g_blkctr/g_done for the next call.
__global__ void scan_lb_kernel() {
    __shared__ int wsum[32];
    __shared__ int s_bid;
    __shared__ int s_prefix;
    __shared__ int s_last;
    int tid = threadIdx.x, lane = tid & 31, w = tid >> 5;
    if (tid == 0) s_bid = atomicAdd(&g_blkctr, 1);
    __syncthreads();
    int b = s_bid;
    int i = b * 1024 + tid;
    int v = (i < NN) ? g_cnt[i] : 0;
    if (i < NN) g_cnt[i] = 0;        // ready for next call's deg
    // block-wide inclusive scan
    int xv = v;
#pragma unroll
    for (int d = 1; d < 32; d <<= 1) {
        int y = __shfl_up_sync(0xffffffffu, xv, d);
        if (lane >= d) xv += y;
    }
    if (lane == 31) wsum[w] = xv;
    __syncthreads();
    if (w == 0) {
        int s = wsum[lane];
#pragma unroll
        for (int d = 1; d < 32; d <<= 1) {
            int y = __shfl_up_sync(0xffffffffu, s, d);
            if (lane >= d) s += y;
        }
        wsum[lane] = s;
    }
    __syncthreads();
    int incl = xv + (w ? wsum[w - 1] : 0);
    int btotal = wsum[31];
    if (tid == 0) {
        unsigned long long d = ((unsigned long long)btotal << 2) | (b == 0 ? 2ull : 1ull);
        atomicExch(&g_desc[b], d);
    }
    if (tid == 0) {
        if (b == 0) {
            s_prefix = 0;
        } else {
            long long pref = 0;
            int p = b - 1;
            while (true) {
                unsigned long long d;
                do { d = atomicAdd(&g_desc[p], 0ull); } while ((d & 3ull) == 0ull);
                pref += (long long)(d >> 2);
                if ((d & 3ull) == 2ull) break;
                p--;
            }
            s_prefix = (int)pref;
        }
    }
    __syncthreads();
    int prefix = s_prefix;
    if (b > 0 && tid == 0) {
        unsigned long long d = ((unsigned long long)(prefix + btotal) << 2) | 2ull;
        atomicExch(&g_desc[b], d);
    }
    int excl = prefix + incl - v;
    if (i < NN) g_off[i] = excl;
    if (b == NBLK - 1 && tid == 1023) g_off[NN] = prefix + btotal;
    // ---- cleanup: last block to finish resets scan metadata for next call ----
    __syncthreads();
    if (tid == 0) {
        int d = atomicAdd(&g_done, 1);
        s_last = (d == NBLK - 1) ? 1 : 0;
    }
    __syncthreads();
    if (s_last) {
        for (int k = tid; k < NBLK; k += 1024) g_desc[k] = 0ull;
        if (tid == 0) { g_blkctr = 0; g_done = 0; }
    }
}

// ---- atomic-free CSR fill: slot = off[dst] + precomputed rank ----
__global__ void fill_kernel(const int* __restrict__ ei) {
    int e = blockIdx.x * blockDim.x + threadIdx.x;
    if (e < NE) {
        unsigned pk = g_rank[e];
        int dst = (int)(pk & 0x1FFFFu);
        if (dst < NN) {
            int r = (int)(pk >> 17);
            int src = ei[e];
            if ((unsigned)src >= NN) src = 0;
            long long p = (long long)g_off[dst] + r;
            if (p < NE) g_csr[p] = src;
        }
    }
}

// ---------------- aggregation: warp per node, mean of 64-dim rows (+tau) ------
template <bool TAU>
__global__ void agg_kernel(const float* __restrict__ featp,
                           const float* __restrict__ tau) {
    const float* __restrict__ feat = TAU ? featp : (const float*)g_h1;
    int lane = threadIdx.x & 31;
    int n = (blockIdx.x * blockDim.x + threadIdx.x) >> 5;
    if (n >= NN) return;
    int beg = g_off[n], end = g_off[n + 1];
    float a0 = 0.f, a1 = 0.f, at = 0.f;
    int j = beg;
    int nfull = (end - beg) >> 5;
    for (int c = 0; c < nfull; c++, j += 32) {
        int s = g_csr[j + lane];
        if (TAU) at += __ldg(tau + s);
#pragma unroll
        for (int k = 0; k < 32; k++) {
            int si = __shfl_sync(0xffffffffu, s, k);
            float2 v = *(const float2*)(feat + (size_t)si * HID + 2 * lane);
            a0 += v.x; a1 += v.y;
        }
    }
    int rem = end - j;
    if (rem > 0) {
        int s = (lane < rem) ? g_csr[j + lane] : 0;
        if (TAU && lane < rem) at += __ldg(tau + s);
        for (int k = 0; k < rem; k++) {
            int si = __shfl_sync(0xffffffffu, s, k);
            float2 v = *(const float2*)(feat + (size_t)si * HID + 2 * lane);
            a0 += v.x; a1 += v.y;
        }
    }
    float inv = 1.f / fmaxf((float)(end - beg), 1.f);
    float2 o; o.x = a0 * inv; o.y = a1 * inv;
    *(float2*)(g_mean + (size_t)n * HID + 2 * lane) = o;
    if (TAU) {
#pragma unroll
        for (int d = 16; d; d >>= 1) at += __shfl_xor_sync(0xffffffffu, at, d);
        if (lane == 0) g_mtau[n] = at * inv;
    }
}

// ---------------- layer-1 GEMM ----------------
__global__ __launch_bounds__(256) void gemm1_kernel(
    const float* __restrict__ x, const float* __restrict__ tau,
    const float* __restrict__ W1l, const float* __restrict__ b1l,
    const float* __restrict__ W1r) {
    __shared__ __align__(16) float sWl[65 * HID];
    __shared__ __align__(16) float sWr[65 * HID];
    __shared__ float sBias[HID];
    __shared__ __align__(16) float sA[8][136];
    int tid = threadIdx.x;
    for (int i = tid; i < 65 * HID; i += 256) { sWl[i] = W1l[i]; sWr[i] = W1r[i]; }
    if (tid < HID) sBias[tid] = b1l[tid];
    int n0 = blockIdx.x * 128;
    int cg = tid & 15, ng = tid >> 4;
    unsigned long long acc2[8][2];
#pragma unroll
    for (int i = 0; i < 8; i++) { acc2[i][0] = 0ull; acc2[i][1] = 0ull; }
    int ldn = n0 + (tid >> 1);
    int ldk = (tid & 1) * 4;
    for (int pass = 0; pass < 2; pass++) {
        const float* __restrict__ A = pass ? x : (const float*)g_mean;
        const float* W = pass ? sWr : sWl;
        for (int kb = 0; kb < HID; kb += 8) {
            __syncthreads();
            float4 v = make_float4(0.f, 0.f, 0.f, 0.f);
            if (ldn < NN) v = *(const float4*)(A + (size_t)ldn * HID + kb + ldk);
            sA[ldk + 0][tid >> 1] = v.x; sA[ldk + 1][tid >> 1] = v.y;
            sA[ldk + 2][tid >> 1] = v.z; sA[ldk + 3][tid >> 1] = v.w;
            __syncthreads();
#pragma unroll
            for (int kk = 0; kk < 8; kk++) {
                float4 b  = *(const float4*)(W + (kb + kk) * HID + 4 * cg);
                float4 q0 = *(const float4*)(&sA[kk][8 * ng]);
                float4 q1 = *(const float4*)(&sA[kk][8 * ng + 4]);
                unsigned long long bp0 = pack2(b.x, b.y);
                unsigned long long bp1 = pack2(b.z, b.w);
                float av[8] = {q0.x, q0.y, q0.z, q0.w, q1.x, q1.y, q1.z, q1.w};
#pragma unroll
                for (int i = 0; i < 8; i++) {
                    unsigned long long ad = pack2(av[i], av[i]);
                    fma2(acc2[i][0], ad, bp0);
                    fma2(acc2[i][1], ad, bp1);
                }
            }
        }
    }
#pragma unroll
    for (int i = 0; i < 8; i++) {
        int nn = n0 + 8 * ng + i;
        if (nn < NN) {
            float mt = g_mtau[nn], tv = __ldg(tau + nn);
            float2 p0 = unpack2(acc2[i][0]);
            float2 p1 = unpack2(acc2[i][1]);
            float accv[4] = {p0.x, p0.y, p1.x, p1.y};
            float4 r;
            float* rr = &r.x;
#pragma unroll
            for (int c = 0; c < 4; c++) {
                int col = 4 * cg + c;
                float o = accv[c] + mt * sWl[64 * HID + col] +
                          tv * sWr[64 * HID + col] + sBias[col];
                rr[c] = fmaxf(o, 0.f);
            }
            *(float4*)(g_h1 + (size_t)nn * HID + 4 * cg) = r;
        }
    }
}

// ---------------- layer-2 GEMM + fused FC head ----------------
__global__ __launch_bounds__(256) void gemm2_kernel(
    const float* __restrict__ W2l, const float* __restrict__ b2l,
    const float* __restrict__ W2r, const float* __restrict__ Wfc,
    const float* __restrict__ bfc, float* __restrict__ out) {
    __shared__ __align__(16) float sWl[HID * HID];
    __shared__ __align__(16) float sWr[HID * HID];
    __shared__ float sBias[HID];
    __shared__ float sFc[HID];
    __shared__ __align__(16) float sA[8][136];
    __shared__ float sRed[128];
    int tid = threadIdx.x;
    for (int i = tid; i < HID * HID; i += 256) { sWl[i] = W2l[i]; sWr[i] = W2r[i]; }
    if (tid < HID) { sBias[tid] = b2l[tid]; sFc[tid] = Wfc[tid]; }
    if (tid < 128) sRed[tid] = 0.f;
    int n0 = blockIdx.x * 128;
    int cg = tid & 15, ng = tid >> 4;
    unsigned long long acc2[8][2];
#pragma unroll
    for (int i = 0; i < 8; i++) { acc2[i][0] = 0ull; acc2[i][1] = 0ull; }
    int ldn = n0 + (tid >> 1);
    int ldk = (tid & 1) * 4;
    for (int pass = 0; pass < 2; pass++) {
        const float* __restrict__ A = pass ? (const float*)g_h1 : (const float*)g_mean;
        const float* W = pass ? sWr : sWl;
        for (int kb = 0; kb < HID; kb += 8) {
            __syncthreads();
            float4 v = make_float4(0.f, 0.f, 0.f, 0.f);
            if (ldn < NN) v = *(const float4*)(A + (size_t)ldn * HID + kb + ldk);
            sA[ldk + 0][tid >> 1] = v.x; sA[ldk + 1][tid >> 1] = v.y;
            sA[ldk + 2][tid >> 1] = v.z; sA[ldk + 3][tid >> 1] = v.w;
            __syncthreads();
#pragma unroll
            for (int kk = 0; kk < 8; kk++) {
                float4 b  = *(const float4*)(W + (kb + kk) * HID + 4 * cg);
                float4 q0 = *(const float4*)(&sA[kk][8 * ng]);
                float4 q1 = *(const float4*)(&sA[kk][8 * ng + 4]);
                unsigned long long bp0 = pack2(b.x, b.y);
                unsigned long long bp1 = pack2(b.z, b.w);
                float av[8] = {q0.x, q0.y, q0.z, q0.w, q1.x, q1.y, q1.z, q1.w};
#pragma unroll
                for (int i = 0; i < 8; i++) {
                    unsigned long long ad = pack2(av[i], av[i]);
                    fma2(acc2[i][0], ad, bp0);
                    fma2(acc2[i][1], ad, bp1);
                }
            }
        }
    }
    float bias0 = __ldg(bfc);
#pragma unroll
    for (int i = 0; i < 8; i++) {
        float2 p0 = unpack2(acc2[i][0]);
        float2 p1 = unpack2(acc2[i][1]);
        float accv[4] = {p0.x, p0.y, p1.x, p1.y};
        float p = 0.f;
#pragma unroll
        for (int c = 0; c < 4; c++) {
            int col = 4 * cg + c;
            float h = fmaxf(accv[c] + sBias[col], 0.f);
            p += h * sFc[col];
        }
        atomicAdd(&sRed[8 * ng + i], p);
    }
    __syncthreads();
    if (tid < 128) {
        int nn = n0 + tid;
        if (nn < NN) out[nn] = sRed[tid] + bias0;
    }
}

// ---------------- launch ----------------
extern "C" void kernel_launch(void* const* d_in, const int* in_sizes, int n_in,
                              void* d_out, int out_size) {
    const float* x    = (const float*)d_in[0];
    const int*   ei   = (const int*)d_in[1];
    const float* tau  = (const float*)d_in[2];
    const float* W1l  = (const float*)d_in[3];
    const float* b1l  = (const float*)d_in[4];
    const float* W1r  = (const float*)d_in[5];
    const float* W2l  = (const float*)d_in[6];
    const float* b2l  = (const float*)d_in[7];
    const float* W2r  = (const float*)d_in[8];
    const float* Wfc  = (const float*)d_in[9];
    const float* bfc  = (const float*)d_in[10];
    float*       out  = (float*)d_out;

    deg_kernel<<<(NE + 255) / 256, 256>>>(ei);
    scan_lb_kernel<<<NBLK, 1024>>>();
    fill_kernel<<<(NE + 255) / 256, 256>>>(ei);

    // layer 1
    agg_kernel<true><<<(NN * 32 + 255) / 256, 256>>>(x, tau);
    gemm1_kernel<<<(NN + 127) / 128, 256>>>(x, tau, W1l, b1l, W1r);

    // layer 2 (+ fused FC head)
    agg_kernel<false><<<(NN * 32 + 255) / 256, 256>>>(x, tau);
    gemm2_kernel<<<(NN + 127) / 128, 256>>>(W2l, b2l, W2r, Wfc, bfc, out);
}